// round 2
// baseline (speedup 1.0000x reference)
#include <cuda_runtime.h>
#include <cstdint>
#include <cstddef>

#define NN 1024
#define DF 16
#define SMEM_BYTES (NN * DF * 4)   // 64 KB: F[b] resident

// ---- f32x2 packed-math helpers (FFMA2 is PTX-only on sm_103a) ----
__device__ __forceinline__ unsigned long long pk2(float x, float y) {
    unsigned long long r;
    asm("mov.b64 %0, {%1, %2};" : "=l"(r) : "f"(x), "f"(y));
    return r;
}
__device__ __forceinline__ void fma2(unsigned long long& d, unsigned long long a, unsigned long long b) {
    asm("fma.rn.f32x2 %0, %1, %2, %0;" : "+l"(d) : "l"(a), "l"(b));
}
__device__ __forceinline__ void upk2(unsigned long long v, float& x, float& y) {
    asm("mov.b64 {%0, %1}, %2;" : "=f"(x), "=f"(y) : "l"(v));
}

__global__ void zero_out_kernel(float* o) { o[threadIdx.x] = 0.0f; }

__global__ void __launch_bounds__(256, 2)
graph_loss_kernel(const float* __restrict__ A,
                  const float* __restrict__ F,
                  float* __restrict__ out) {
    extern __shared__ float F_s[];          // [1024][16] fp32
    const int tid = threadIdx.x;
    const int b   = blockIdx.x >> 2;        // batch
    const int blk = blockIdx.x & 3;         // 256-row slab within batch

    // ---- Load F[b] into shared (64 KB), vectorized ----
    {
        const float4* src = reinterpret_cast<const float4*>(F + (size_t)b * NN * DF);
        float4* dst = reinterpret_cast<float4*>(F_s);
        #pragma unroll
        for (int i = 0; i < (NN * DF / 4) / 256; ++i)
            dst[tid + i * 256] = src[tid + i * 256];
    }
    __syncthreads();

    // One thread owns one full row: streams A[row][*] via LDG.128, F[j] via broadcast LDS.
    const int row = blk * 256 + tid;
    const float4* __restrict__ arow =
        reinterpret_cast<const float4*>(A + (size_t)b * NN * NN + (size_t)row * NN);

    unsigned long long acc[8];              // AF[0..15] as 8 f32x2
    #pragma unroll
    for (int k = 0; k < 8; ++k) acc[k] = 0ull;
    unsigned long long dss = 0ull;          // {deg, sum(a^2)}
    const float onef = 1.0f;

    #define BODY(av, jj) {                                                     \
        unsigned long long pa = pk2((av), (av));                               \
        fma2(dss, pa, pk2(onef, (av)));                                        \
        const ulonglong2* fp = reinterpret_cast<const ulonglong2*>(F_s + (jj) * DF); \
        ulonglong2 q0 = fp[0], q1 = fp[1], q2 = fp[2], q3 = fp[3];             \
        fma2(acc[0], pa, q0.x); fma2(acc[1], pa, q0.y);                        \
        fma2(acc[2], pa, q1.x); fma2(acc[3], pa, q1.y);                        \
        fma2(acc[4], pa, q2.x); fma2(acc[5], pa, q2.y);                        \
        fma2(acc[6], pa, q3.x); fma2(acc[7], pa, q3.y); }

    #pragma unroll 1
    for (int c = 0; c < NN / 4; c += 4) {
        // Batch 4 LDG.128 up front -> MLP 4 per thread, rest hidden by 16 warps/SM
        float4 a0 = arow[c + 0];
        float4 a1 = arow[c + 1];
        float4 a2 = arow[c + 2];
        float4 a3 = arow[c + 3];
        const int j = 4 * c;
        BODY(a0.x, j +  0) BODY(a0.y, j +  1) BODY(a0.z, j +  2) BODY(a0.w, j +  3)
        BODY(a1.x, j +  4) BODY(a1.y, j +  5) BODY(a1.z, j +  6) BODY(a1.w, j +  7)
        BODY(a2.x, j +  8) BODY(a2.y, j +  9) BODY(a2.z, j + 10) BODY(a2.w, j + 11)
        BODY(a3.x, j + 12) BODY(a3.y, j + 13) BODY(a3.z, j + 14) BODY(a3.w, j + 15)
    }
    #undef BODY

    // ---- Finalize: per-row loss contribution (all thread-private) ----
    const float c1 = 0.2f / (1024.0f * 1024.0f);   // smoothness / N^2
    const float c2 = 0.1f / 1024.0f;               // degree / N
    const float c3 = 0.1f / (1024.0f * 1024.0f);   // sparsity / N^2

    float deg, ss;
    upk2(dss, deg, ss);
    const float* fr = F_s + row * DF;
    float t1 = 0.0f, t2 = 0.0f;
    #pragma unroll
    for (int k = 0; k < 8; ++k) {
        float af0, af1;
        upk2(acc[k], af0, af1);
        float f0 = fr[2 * k], f1 = fr[2 * k + 1];
        t1 += f0 * f0 + f1 * f1;     // ||f_n||^2
        t2 += f0 * af0 + f1 * af1;   // <f_n, (A F)_n>
    }
    float contrib = c1 * (deg * t1 - t2) - c2 * logf(deg + 1e-12f) + c3 * ss;

    #pragma unroll
    for (int o = 16; o; o >>= 1)
        contrib += __shfl_xor_sync(0xffffffffu, contrib, o);
    if ((tid & 31) == 0)
        atomicAdd(out + b, contrib);
}

extern "C" void kernel_launch(void* const* d_in, const int* in_sizes, int n_in,
                              void* d_out, int out_size) {
    const float* A = (const float*)d_in[0];   // out_adj [64,1024,1024]
    const float* F = (const float*)d_in[1];   // features [64,1024,16]
    float* out = (float*)d_out;               // [64]

    static bool attr_set = false;
    if (!attr_set) {
        cudaFuncSetAttribute(graph_loss_kernel,
                             cudaFuncAttributeMaxDynamicSharedMemorySize,
                             SMEM_BYTES);
        attr_set = true;
    }

    zero_out_kernel<<<1, 64>>>(out);
    graph_loss_kernel<<<256, 256, SMEM_BYTES>>>(A, F, out);
}

// round 3
// speedup vs baseline: 1.0285x; 1.0285x over previous
#include <cuda_runtime.h>
#include <cstdint>
#include <cstddef>

#define NN 1024
#define DF 16
#define C 16                    // columns per staged chunk
#define STR 20                  // staged row stride in floats (80 B, 16B-aligned for cp16)
#define BUF (64 * STR)          // floats per staging buffer (64 rows)
#define NCH 32                  // chunks per warp (512 cols / 16)

// Interleaved F pairs: G[b][jj][2k + (j&1)] = F[b][2jj + (j&1)][k]
__device__ float Gbuf[64 * 512 * 32];   // 4 MB static scratch

// ---- f32x2 packed helpers ----
__device__ __forceinline__ void fma2(unsigned long long& d, unsigned long long a, unsigned long long b) {
    asm("fma.rn.f32x2 %0, %1, %2, %0;" : "+l"(d) : "l"(a), "l"(b));
}
__device__ __forceinline__ void add2(unsigned long long& d, unsigned long long a) {
    asm("add.rn.f32x2 %0, %0, %1;" : "+l"(d) : "l"(a));
}
__device__ __forceinline__ void upk2(unsigned long long v, float& x, float& y) {
    asm("mov.b64 {%0, %1}, %2;" : "=f"(x), "=f"(y) : "l"(v));
}
__device__ __forceinline__ void cp16(unsigned dst, const float* src) {
    asm volatile("cp.async.cg.shared.global [%0], [%1], 16;" :: "r"(dst), "l"(src));
}

__global__ void zero_out_kernel(float* o) { o[threadIdx.x] = 0.0f; }

__global__ void build_G_kernel(const float* __restrict__ F) {
    const int b = blockIdx.x;
    const float4* src = reinterpret_cast<const float4*>(F + (size_t)b * NN * DF);
    float* g = Gbuf + (size_t)b * NN * DF;
    for (int i = threadIdx.x; i < NN * DF / 4; i += blockDim.x) {
        float4 v = src[i];
        int j = i >> 2, kq = i & 3;
        float* dst = g + (j >> 1) * 32 + (j & 1) + 8 * kq;
        dst[0] = v.x; dst[2] = v.y; dst[4] = v.z; dst[6] = v.w;
    }
}

__global__ void __launch_bounds__(128, 4)
graph_loss_kernel(const float* __restrict__ A,
                  const float* __restrict__ F,
                  float* __restrict__ out) {
    extern __shared__ float smem[];     // 4 warps * 2 * BUF floats = 40960 B
    const int tid  = threadIdx.x;
    const int lane = tid & 31;
    const int wid  = tid >> 5;
    const int rowg = wid >> 1;          // 0/1: 64-row group
    const int colg = wid & 1;           // 0/1: 512-col group
    const int b    = blockIdx.x >> 3;
    const int slab = blockIdx.x & 7;    // 128-row slab within batch

    const int row0 = slab * 128 + rowg * 64;
    const int col0 = colg * 512;
    const float* Ab = A + (size_t)b * NN * NN + (size_t)row0 * NN + col0;

    float* buf = smem + wid * 2 * BUF;
    const unsigned sb = (unsigned)__cvta_generic_to_shared(smem) + wid * (2 * BUF * 4);
    const ulonglong2* __restrict__ Gp =
        reinterpret_cast<const ulonglong2*>(Gbuf + (size_t)b * NN * DF + col0 * 16);

    unsigned long long acc0[16], acc1[16];
    #pragma unroll
    for (int k = 0; k < 16; ++k) { acc0[k] = 0ull; acc1[k] = 0ull; }
    unsigned long long d0 = 0ull, s0 = 0ull, d1 = 0ull, s1 = 0ull;

    // cp.async: stage 64 rows x 16 cols (4 KB) of A, transposable via LDS
    auto issue = [&](int c, int bufi) {
        const int cbase = c * C;
        #pragma unroll
        for (int k = 0; k < 8; ++k) {
            int linear = k * 32 + lane;
            int row = linear >> 2, c16 = linear & 3;
            cp16(sb + bufi * (BUF * 4) + row * (STR * 4) + c16 * 16,
                 Ab + (size_t)row * NN + cbase + c16 * 4);
        }
        asm volatile("cp.async.commit_group;");
    };

    issue(0, 0);

    for (int c = 0; c < NCH; ++c) {
        const int cur = c & 1;
        __syncwarp();
        if (c < NCH - 1) {
            issue(c + 1, cur ^ 1);
            asm volatile("cp.async.wait_group 1;" ::: "memory");
        } else {
            asm volatile("cp.async.wait_group 0;" ::: "memory");
        }
        __syncwarp();

        const float* bf = buf + cur * BUF;
        const ulonglong2* gc = Gp + (size_t)c * 8 * 8;   // 8 jj per chunk, 8 u2 per jj

        #pragma unroll
        for (int jjl = 0; jjl < 8; ++jjl) {
            const ulonglong2* g = gc + jjl * 8;
            ulonglong2 g0 = __ldg(g + 0), g1 = __ldg(g + 1);
            ulonglong2 g2 = __ldg(g + 2), g3 = __ldg(g + 3);
            ulonglong2 g4 = __ldg(g + 4), g5 = __ldg(g + 5);
            ulonglong2 g6 = __ldg(g + 6), g7 = __ldg(g + 7);

            unsigned long long a0 = *reinterpret_cast<const unsigned long long*>(
                bf + lane * STR + jjl * 2);
            unsigned long long a1 = *reinterpret_cast<const unsigned long long*>(
                bf + (lane + 32) * STR + jjl * 2);

            add2(d0, a0); fma2(s0, a0, a0);
            add2(d1, a1); fma2(s1, a1, a1);

            fma2(acc0[0],  a0, g0.x); fma2(acc0[1],  a0, g0.y);
            fma2(acc0[2],  a0, g1.x); fma2(acc0[3],  a0, g1.y);
            fma2(acc0[4],  a0, g2.x); fma2(acc0[5],  a0, g2.y);
            fma2(acc0[6],  a0, g3.x); fma2(acc0[7],  a0, g3.y);
            fma2(acc0[8],  a0, g4.x); fma2(acc0[9],  a0, g4.y);
            fma2(acc0[10], a0, g5.x); fma2(acc0[11], a0, g5.y);
            fma2(acc0[12], a0, g6.x); fma2(acc0[13], a0, g6.y);
            fma2(acc0[14], a0, g7.x); fma2(acc0[15], a0, g7.y);

            fma2(acc1[0],  a1, g0.x); fma2(acc1[1],  a1, g0.y);
            fma2(acc1[2],  a1, g1.x); fma2(acc1[3],  a1, g1.y);
            fma2(acc1[4],  a1, g2.x); fma2(acc1[5],  a1, g2.y);
            fma2(acc1[6],  a1, g3.x); fma2(acc1[7],  a1, g3.y);
            fma2(acc1[8],  a1, g4.x); fma2(acc1[9],  a1, g4.y);
            fma2(acc1[10], a1, g5.x); fma2(acc1[11], a1, g5.y);
            fma2(acc1[12], a1, g6.x); fma2(acc1[13], a1, g6.y);
            fma2(acc1[14], a1, g7.x); fma2(acc1[15], a1, g7.y);
        }
    }

    // ---- Combine column halves via smem, then finalize ----
    __syncthreads();                    // staging no longer needed; reuse as P
    float* P = smem;                    // P[colg][128][18]
    #pragma unroll
    for (int r = 0; r < 2; ++r) {
        const unsigned long long* ac = r ? acc1 : acc0;
        float* p = P + (colg * 128 + rowg * 64 + lane + r * 32) * 18;
        #pragma unroll
        for (int k = 0; k < 16; ++k) {
            float lo, hi; upk2(ac[k], lo, hi);
            p[k] = lo + hi;
        }
        float dl, dh, sl, sh;
        upk2(r ? d1 : d0, dl, dh);
        upk2(r ? s1 : s0, sl, sh);
        p[16] = dl + dh;
        p[17] = sl + sh;
    }
    __syncthreads();

    const float c1 = 0.2f / (1024.0f * 1024.0f);
    const float c2 = 0.1f / 1024.0f;
    const float c3 = 0.1f / (1024.0f * 1024.0f);

    // thread t finalizes CTA-local row t
    const float* p0 = P + tid * 18;
    const float* p1 = P + (128 + tid) * 18;
    const int grow = slab * 128 + tid;
    const float4* fr = reinterpret_cast<const float4*>(F + (size_t)b * NN * DF + (size_t)grow * DF);

    float t1 = 0.0f, t2 = 0.0f;
    #pragma unroll
    for (int q = 0; q < 4; ++q) {
        float4 f = __ldg(fr + q);
        t1 += f.x * f.x + f.y * f.y + f.z * f.z + f.w * f.w;
        t2 += f.x * (p0[4*q+0] + p1[4*q+0]) + f.y * (p0[4*q+1] + p1[4*q+1])
            + f.z * (p0[4*q+2] + p1[4*q+2]) + f.w * (p0[4*q+3] + p1[4*q+3]);
    }
    float deg = p0[16] + p1[16];
    float ss  = p0[17] + p1[17];
    float contrib = c1 * (deg * t1 - t2) - c2 * logf(deg + 1e-12f) + c3 * ss;

    #pragma unroll
    for (int o = 16; o; o >>= 1)
        contrib += __shfl_xor_sync(0xffffffffu, contrib, o);
    if (lane == 0)
        atomicAdd(out + b, contrib);
}

extern "C" void kernel_launch(void* const* d_in, const int* in_sizes, int n_in,
                              void* d_out, int out_size) {
    const float* A = (const float*)d_in[0];   // out_adj [64,1024,1024]
    const float* F = (const float*)d_in[1];   // features [64,1024,16]
    float* out = (float*)d_out;               // [64]

    zero_out_kernel<<<1, 64>>>(out);
    build_G_kernel<<<64, 256>>>(F);
    graph_loss_kernel<<<512, 128, 4 * 2 * BUF * 4>>>(A, F, out);
}

// round 4
// speedup vs baseline: 1.1737x; 1.1412x over previous
#include <cuda_runtime.h>
#include <cstdint>
#include <cstddef>

#define NN   1024
#define DF   16
#define CCH  16                      // A columns per staged chunk
#define STR  17                      // staged row stride in words (odd -> conflict-free)
#define ROWSC 512                    // rows per CTA tile
#define COLSC 512                    // cols per CTA tile
#define NCHUNK (COLSC / CCH)         // 32
#define STAGE_FLTS (ROWSC * STR)     // 8704 floats per buffer
#define SMEM_BYTES ((COLSC * DF + 2 * STAGE_FLTS) * 4)   // 32768B + 69632B = 102400B

__device__ float degP[2][64][NN];    // partial row degrees per column-half (512 KB scratch)

// ---- f32x2 packed helpers ----
__device__ __forceinline__ unsigned long long pk2(float x, float y) {
    unsigned long long r;
    asm("mov.b64 %0, {%1, %2};" : "=l"(r) : "f"(x), "f"(y));
    return r;
}
__device__ __forceinline__ void fma2(unsigned long long& d, unsigned long long a, unsigned long long b) {
    asm("fma.rn.f32x2 %0, %1, %2, %0;" : "+l"(d) : "l"(a), "l"(b));
}
__device__ __forceinline__ void upk2(unsigned long long v, float& x, float& y) {
    asm("mov.b64 {%0, %1}, %2;" : "=f"(x), "=f"(y) : "l"(v));
}
__device__ __forceinline__ void cp4(unsigned dst, const float* src) {
    asm volatile("cp.async.ca.shared.global [%0], [%1], 4;" :: "r"(dst), "l"(src));
}

__global__ void zero_out_kernel(float* o) { o[threadIdx.x] = 0.0f; }

__global__ void finalize_kernel(float* out) {
    const int b = blockIdx.x;
    const int tid = threadIdx.x;
    float s = 0.0f;
    #pragma unroll
    for (int r = tid; r < NN; r += 256) {
        float d = degP[0][b][r] + degP[1][b][r];
        s += logf(d + 1e-12f);
    }
    #pragma unroll
    for (int o = 16; o; o >>= 1)
        s += __shfl_xor_sync(0xffffffffu, s, o);
    if ((tid & 31) == 0)
        atomicAdd(out + b, (-0.1f / 1024.0f) * s);
}

__global__ void __launch_bounds__(256, 2)
graph_loss_kernel(const float* __restrict__ A,
                  const float* __restrict__ F,
                  float* __restrict__ out) {
    extern __shared__ float smem[];
    float* F_s = smem;                      // [512][16] fp32 (this CTA's column range)
    float* stage = smem + COLSC * DF;       // [2][512][17]

    const int tid  = threadIdx.x;
    const int lane = tid & 31;
    const int wid  = tid >> 5;
    const int b    = blockIdx.x >> 2;
    const int rowh = (blockIdx.x >> 1) & 1;
    const int colh = blockIdx.x & 1;

    const int rowbase = rowh * ROWSC;
    const int colbase = colh * COLSC;
    const float* Acta = A + (size_t)b * NN * NN + (size_t)rowbase * NN + colbase;

    const unsigned sb = (unsigned)__cvta_generic_to_shared(stage);

    // CTA-cooperative cp.async of one 512x16 A chunk
    auto issue = [&](int c, int bufi) {
        const float* src0 = Acta + c * CCH;
        const unsigned d0 = sb + bufi * (STAGE_FLTS * 4);
        #pragma unroll
        for (int k = 0; k < 32; ++k) {
            int linear = k * 256 + tid;
            int row = linear >> 4;
            int col = linear & 15;
            cp4(d0 + (row * STR + col) * 4, src0 + (size_t)row * NN + col);
        }
        asm volatile("cp.async.commit_group;");
    };

    issue(0, 0);    // overlap with F load below

    // Load this CTA's F column-range into shared: 512 rows x 16 = 32 KB
    {
        const float4* src = reinterpret_cast<const float4*>(
            F + (size_t)b * NN * DF + (size_t)colbase * DF);
        float4* dst = reinterpret_cast<float4*>(F_s);
        #pragma unroll
        for (int i = 0; i < (COLSC * DF / 4) / 256; ++i)
            dst[tid + i * 256] = src[tid + i * 256];
    }

    // Per-warp rows: wid*64 + lane and +32 (CTA-local)
    const int r0off = (wid * 64 + lane) * STR;
    const int r1off = (wid * 64 + lane + 32) * STR;

    unsigned long long acc0[8], acc1[8];
    #pragma unroll
    for (int k = 0; k < 8; ++k) { acc0[k] = 0ull; acc1[k] = 0ull; }
    float deg0 = 0.0f, ss0 = 0.0f, deg1 = 0.0f, ss1 = 0.0f;

    for (int c = 0; c < NCHUNK; ++c) {
        const int cur = c & 1;
        if (c < NCHUNK - 1) {
            issue(c + 1, cur ^ 1);
            asm volatile("cp.async.wait_group 1;" ::: "memory");
        } else {
            asm volatile("cp.async.wait_group 0;" ::: "memory");
        }
        __syncthreads();                       // cp data visible to all warps

        const float* st = stage + cur * STAGE_FLTS;
        const float* fc = F_s + c * CCH * DF;

        #pragma unroll
        for (int j = 0; j < CCH; ++j) {
            float a0 = st[r0off + j];
            float a1 = st[r1off + j];
            const ulonglong2* fp = reinterpret_cast<const ulonglong2*>(fc + j * DF);
            ulonglong2 q0 = fp[0], q1 = fp[1], q2 = fp[2], q3 = fp[3];

            deg0 += a0; ss0 = fmaf(a0, a0, ss0);
            deg1 += a1; ss1 = fmaf(a1, a1, ss1);
            unsigned long long pa0 = pk2(a0, a0);
            unsigned long long pa1 = pk2(a1, a1);

            fma2(acc0[0], pa0, q0.x); fma2(acc0[1], pa0, q0.y);
            fma2(acc0[2], pa0, q1.x); fma2(acc0[3], pa0, q1.y);
            fma2(acc0[4], pa0, q2.x); fma2(acc0[5], pa0, q2.y);
            fma2(acc0[6], pa0, q3.x); fma2(acc0[7], pa0, q3.y);

            fma2(acc1[0], pa1, q0.x); fma2(acc1[1], pa1, q0.y);
            fma2(acc1[2], pa1, q1.x); fma2(acc1[3], pa1, q1.y);
            fma2(acc1[4], pa1, q2.x); fma2(acc1[5], pa1, q2.y);
            fma2(acc1[6], pa1, q3.x); fma2(acc1[7], pa1, q3.y);
        }
        __syncthreads();                       // all reads done before buffer reuse
    }

    // ---- Epilogue: linear terms + partial-deg scratch ----
    const float c1 = 0.2f / (1024.0f * 1024.0f);
    const float c3 = 0.1f / (1024.0f * 1024.0f);

    float contrib = 0.0f;
    #pragma unroll
    for (int r = 0; r < 2; ++r) {
        const unsigned long long* ac = r ? acc1 : acc0;
        const float deg = r ? deg1 : deg0;
        const float ss  = r ? ss1  : ss0;
        const int grow = rowbase + wid * 64 + lane + r * 32;
        const float4* fr = reinterpret_cast<const float4*>(
            F + (size_t)b * NN * DF + (size_t)grow * DF);
        float t1 = 0.0f, t2 = 0.0f;
        #pragma unroll
        for (int q = 0; q < 4; ++q) {
            float4 f = __ldg(fr + q);
            float lo0, hi0, lo1, hi1;
            upk2(ac[2 * q],     lo0, hi0);
            upk2(ac[2 * q + 1], lo1, hi1);
            t1 += f.x * f.x + f.y * f.y + f.z * f.z + f.w * f.w;
            t2 += f.x * lo0 + f.y * hi0 + f.z * lo1 + f.w * hi1;
        }
        degP[colh][b][grow] = deg;
        contrib += c1 * (deg * t1 - t2) + c3 * ss;
    }

    #pragma unroll
    for (int o = 16; o; o >>= 1)
        contrib += __shfl_xor_sync(0xffffffffu, contrib, o);
    if (lane == 0)
        atomicAdd(out + b, contrib);
}

extern "C" void kernel_launch(void* const* d_in, const int* in_sizes, int n_in,
                              void* d_out, int out_size) {
    const float* A = (const float*)d_in[0];   // out_adj [64,1024,1024]
    const float* F = (const float*)d_in[1];   // features [64,1024,16]
    float* out = (float*)d_out;               // [64]

    static bool attr_set = false;
    if (!attr_set) {
        cudaFuncSetAttribute(graph_loss_kernel,
                             cudaFuncAttributeMaxDynamicSharedMemorySize,
                             SMEM_BYTES);
        attr_set = true;
    }

    zero_out_kernel<<<1, 64>>>(out);
    graph_loss_kernel<<<256, 256, SMEM_BYTES>>>(A, F, out);
    finalize_kernel<<<64, 256>>>(out);
}

// round 5
// speedup vs baseline: 1.9112x; 1.6283x over previous
#include <cuda_runtime.h>
#include <cstdint>
#include <cstddef>

#define NN    1024
#define DF    16
#define CCOLS 8                         // A columns per staged chunk
#define RSTRF 12                        // staged row stride in floats (48 B: conflict-free LDS.128)
#define NCH   64                        // chunks per warp (512 cols / 8)
#define DEPTH 3
#define WBUF  (64 * RSTRF)              // 768 floats = 3 KB per buffer
#define FS_FLOATS (512 * DF)            // 8192 floats = 32 KB
#define SMEM_BYTES ((FS_FLOATS + 8 * DEPTH * WBUF) * 4)   // 32768 + 73728 = 106496 B

__device__ float degP[2][64][NN];       // partial row degrees per column-half
__device__ float contribP[4][64];       // per-CTA linear partials

// ---- f32x2 packed helpers ----
__device__ __forceinline__ unsigned long long pk2(float x, float y) {
    unsigned long long r;
    asm("mov.b64 %0, {%1, %2};" : "=l"(r) : "f"(x), "f"(y));
    return r;
}
__device__ __forceinline__ void fma2(unsigned long long& d, unsigned long long a, unsigned long long b) {
    asm("fma.rn.f32x2 %0, %1, %2, %0;" : "+l"(d) : "l"(a), "l"(b));
}
__device__ __forceinline__ void upk2(unsigned long long v, float& x, float& y) {
    asm("mov.b64 {%0, %1}, %2;" : "=f"(x), "=f"(y) : "l"(v));
}
__device__ __forceinline__ void cp16(unsigned dst, const float* src) {
    asm volatile("cp.async.cg.shared.global [%0], [%1], 16;" :: "r"(dst), "l"(src));
}

__global__ void finalize_kernel(float* out) {
    const int b = blockIdx.x;
    const int tid = threadIdx.x;
    __shared__ float red[8];
    float s = 0.0f;
    for (int r = tid; r < NN; r += 256) {
        float d = degP[0][b][r] + degP[1][b][r];
        s += logf(d + 1e-12f);
    }
    #pragma unroll
    for (int o = 16; o; o >>= 1)
        s += __shfl_xor_sync(0xffffffffu, s, o);
    if ((tid & 31) == 0) red[tid >> 5] = s;
    __syncthreads();
    if (tid == 0) {
        float t = 0.0f;
        #pragma unroll
        for (int w = 0; w < 8; ++w) t += red[w];
        out[b] = contribP[0][b] + contribP[1][b] + contribP[2][b] + contribP[3][b]
               - (0.1f / 1024.0f) * t;
    }
}

__global__ void __launch_bounds__(256, 2)
graph_loss_kernel(const float* __restrict__ A,
                  const float* __restrict__ F) {
    extern __shared__ float smem[];
    float* F_s = smem;                          // [512][16] this CTA's column range
    float* stage = smem + FS_FLOATS;            // [8 warps][DEPTH][64][12]

    const int tid  = threadIdx.x;
    const int lane = tid & 31;
    const int wid  = tid >> 5;
    const int b    = blockIdx.x >> 2;
    const int rowh = (blockIdx.x >> 1) & 1;
    const int colh = blockIdx.x & 1;

    const int rowbase = rowh * 512 + wid * 64;      // this warp's first row
    const int colbase = colh * 512;
    const float* __restrict__ Aw = A + (size_t)b * NN * NN + (size_t)rowbase * NN + colbase;

    float* wbuf = stage + wid * (DEPTH * WBUF);
    const unsigned sb = (unsigned)__cvta_generic_to_shared(wbuf);

    // issue one 64x8 chunk into buffer slot (4 cp16 per lane)
    auto issue = [&](int c, int slot) {
        const float* src0 = Aw + c * CCOLS;
        const unsigned d0 = sb + slot * (WBUF * 4);
        #pragma unroll
        for (int k = 0; k < 4; ++k) {
            int linear = k * 32 + lane;
            int row = linear >> 1;
            int u   = linear & 1;
            cp16(d0 + (row * RSTRF + u * 4) * 4, src0 + (size_t)row * NN + u * 4);
        }
        asm volatile("cp.async.commit_group;");
    };

    issue(0, 0);
    issue(1, 1);

    // Load this CTA's F column-range into shared: 512 x 16 = 32 KB
    {
        const float4* src = reinterpret_cast<const float4*>(
            F + (size_t)b * NN * DF + (size_t)colbase * DF);
        float4* dst = reinterpret_cast<float4*>(F_s);
        #pragma unroll
        for (int i = 0; i < (FS_FLOATS / 4) / 256; ++i)
            dst[tid + i * 256] = src[tid + i * 256];
    }
    __syncthreads();

    unsigned long long acc0[8], acc1[8];
    #pragma unroll
    for (int k = 0; k < 8; ++k) { acc0[k] = 0ull; acc1[k] = 0ull; }
    float deg0 = 0.0f, ss0 = 0.0f, deg1 = 0.0f, ss1 = 0.0f;

    const int r0 = lane * RSTRF;
    const int r1 = (lane + 32) * RSTRF;

    auto compute = [&](int slot, int c) {
        const float* bf = wbuf + slot * WBUF;
        const float* fc = F_s + c * CCOLS * DF;
        #pragma unroll
        for (int t = 0; t < 2; ++t) {
            float4 a0 = *reinterpret_cast<const float4*>(bf + r0 + t * 4);
            float4 a1 = *reinterpret_cast<const float4*>(bf + r1 + t * 4);
            #pragma unroll
            for (int e = 0; e < 4; ++e) {
                const float av0 = (e == 0) ? a0.x : (e == 1) ? a0.y : (e == 2) ? a0.z : a0.w;
                const float av1 = (e == 0) ? a1.x : (e == 1) ? a1.y : (e == 2) ? a1.z : a1.w;
                const ulonglong2* fp = reinterpret_cast<const ulonglong2*>(fc + (t * 4 + e) * DF);
                ulonglong2 q0 = fp[0], q1 = fp[1], q2 = fp[2], q3 = fp[3];

                deg0 += av0; ss0 = fmaf(av0, av0, ss0);
                deg1 += av1; ss1 = fmaf(av1, av1, ss1);
                unsigned long long pa0 = pk2(av0, av0);
                unsigned long long pa1 = pk2(av1, av1);

                fma2(acc0[0], pa0, q0.x); fma2(acc0[1], pa0, q0.y);
                fma2(acc0[2], pa0, q1.x); fma2(acc0[3], pa0, q1.y);
                fma2(acc0[4], pa0, q2.x); fma2(acc0[5], pa0, q2.y);
                fma2(acc0[6], pa0, q3.x); fma2(acc0[7], pa0, q3.y);

                fma2(acc1[0], pa1, q0.x); fma2(acc1[1], pa1, q0.y);
                fma2(acc1[2], pa1, q1.x); fma2(acc1[3], pa1, q1.y);
                fma2(acc1[4], pa1, q2.x); fma2(acc1[5], pa1, q2.y);
                fma2(acc1[6], pa1, q3.x); fma2(acc1[7], pa1, q3.y);
            }
        }
    };

    int cur = 0;        // c % DEPTH
    int nxt = 2;        // (c+2) % DEPTH
    #pragma unroll 1
    for (int c = 0; c < NCH - 2; ++c) {
        issue(c + 2, nxt);
        asm volatile("cp.async.wait_group 2;" ::: "memory");
        __syncwarp();
        compute(cur, c);
        __syncwarp();
        cur = (cur == DEPTH - 1) ? 0 : cur + 1;
        nxt = (nxt == DEPTH - 1) ? 0 : nxt + 1;
    }
    asm volatile("cp.async.wait_group 1;" ::: "memory");
    __syncwarp();
    compute(cur, NCH - 2);
    cur = (cur == DEPTH - 1) ? 0 : cur + 1;
    asm volatile("cp.async.wait_group 0;" ::: "memory");
    __syncwarp();
    compute(cur, NCH - 1);

    // ---- Epilogue: linear terms; deg halves to scratch; CTA partial ----
    const float c1 = 0.2f / (1024.0f * 1024.0f);
    const float c3 = 0.1f / (1024.0f * 1024.0f);

    float contrib = 0.0f;
    #pragma unroll
    for (int r = 0; r < 2; ++r) {
        const unsigned long long* ac = r ? acc1 : acc0;
        const float deg = r ? deg1 : deg0;
        const float ss  = r ? ss1  : ss0;
        const int grow = rowbase + lane + r * 32;
        const float4* fr = reinterpret_cast<const float4*>(
            F + (size_t)b * NN * DF + (size_t)grow * DF);
        float t1 = 0.0f, t2 = 0.0f;
        #pragma unroll
        for (int q = 0; q < 4; ++q) {
            float4 f = __ldg(fr + q);
            float lo0, hi0, lo1, hi1;
            upk2(ac[2 * q],     lo0, hi0);
            upk2(ac[2 * q + 1], lo1, hi1);
            t1 += f.x * f.x + f.y * f.y + f.z * f.z + f.w * f.w;
            t2 += f.x * lo0 + f.y * hi0 + f.z * lo1 + f.w * hi1;
        }
        degP[colh][b][grow] = deg;
        contrib += c1 * (deg * t1 - t2) + c3 * ss;
    }

    #pragma unroll
    for (int o = 16; o; o >>= 1)
        contrib += __shfl_xor_sync(0xffffffffu, contrib, o);

    __syncthreads();                 // stage region no longer needed
    float* red = smem;               // reuse smem for CTA reduction
    if (lane == 0) red[wid] = contrib;
    __syncthreads();
    if (tid == 0) {
        float t = 0.0f;
        #pragma unroll
        for (int w = 0; w < 8; ++w) t += red[w];
        contribP[rowh * 2 + colh][b] = t;
    }
}

extern "C" void kernel_launch(void* const* d_in, const int* in_sizes, int n_in,
                              void* d_out, int out_size) {
    const float* A = (const float*)d_in[0];   // out_adj [64,1024,1024]
    const float* F = (const float*)d_in[1];   // features [64,1024,16]
    float* out = (float*)d_out;               // [64]

    static bool attr_set = false;
    if (!attr_set) {
        cudaFuncSetAttribute(graph_loss_kernel,
                             cudaFuncAttributeMaxDynamicSharedMemorySize,
                             SMEM_BYTES);
        attr_set = true;
    }

    graph_loss_kernel<<<256, 256, SMEM_BYTES>>>(A, F);
    finalize_kernel<<<64, 256>>>(out);
}